// round 1
// baseline (speedup 1.0000x reference)
#include <cuda_runtime.h>
#include <cstdint>
#include <cstdio>

#define N32   32
#define M64   64
#define BSZ   512
#define ALPHA 1.0f
#define BETA  1.0f

// ----------------------------- device scratch -----------------------------
__device__ double gPa[32 * 64];      // GJ augmented for P
__device__ double gPinv[32 * 32];
__device__ double gGa[32 * 64];      // GJ augmented for G = H^T H
__device__ double gGinv[32 * 32];
__device__ double gE[32 * 64];       // E = Pinv H^T
__device__ double gHinvd[32 * 64];   // Hinv = Ginv H^T
__device__ double gD[64 * 64];       // D = H Pinv H^T
__device__ double gCd[32 * 32];      // C = Pinv H^T H (similar to SPD)
__device__ float  gCf[2][32 * 32];   // squaring buffers
__device__ double gY[64], gZ[64];
__device__ double gScalD[4];
__device__ float  gScalF[4];
__device__ float  gDf[64 * 64];
__device__ float  gHinvf[32 * 68];   // padded stride 68 (16B-aligned rows)
__device__ float  gMu[BSZ * 64];
__device__ float  gCvec[BSZ * 32];
__device__ int    gItersDefault = 1000;

// ----------------------------- helpers -----------------------------
__device__ __forceinline__ unsigned long long ffma2(unsigned long long a,
                                                    unsigned long long b,
                                                    unsigned long long c) {
    unsigned long long d;
    asm("fma.rn.f32x2 %0, %1, %2, %3;" : "=l"(d) : "l"(a), "l"(b), "l"(c));
    return d;
}
__device__ __forceinline__ float hsum2(unsigned long long a) {
    float lo, hi;
    asm("mov.b64 {%0, %1}, %2;" : "=f"(lo), "=f"(hi) : "l"(a));
    return lo + hi;
}

// Gauss-Jordan on [32 x 64] augmented matrix (full elimination), 128 threads.
__device__ void gj32(double* Aug) {
    const int tid = threadIdx.x;
    for (int p = 0; p < 32; ++p) {
        __syncthreads();
        double pv = Aug[p * 64 + p];
        __syncthreads();
        double ipv = 1.0 / pv;
        for (int c = tid; c < 64; c += 128) Aug[p * 64 + c] *= ipv;
        __syncthreads();
        int r  = tid >> 2;
        int cs = (tid & 3) * 16;
        double f = Aug[r * 64 + p];
        __syncthreads();
        if (r != p) {
            for (int c = cs; c < cs + 16; ++c)
                Aug[r * 64 + c] -= f * Aug[p * 64 + c];
        }
    }
    __syncthreads();
}

// ----------------------------- preprocessing (1 CTA, fp64) -----------------------------
__global__ void preproc_kernel(const float* __restrict__ P, const float* __restrict__ H) {
    const int tid = threadIdx.x;
    __shared__ double sred[128];
    __shared__ double sval[4];
    __shared__ int sidx;

    // P augmented -> invert
    for (int i = tid; i < 32 * 64; i += 128) {
        int r = i >> 6, c = i & 63;
        gPa[i] = (c < 32) ? (double)P[r * 32 + c] : ((c - 32 == r) ? 1.0 : 0.0);
    }
    __syncthreads();
    gj32(gPa);
    for (int i = tid; i < 1024; i += 128) gPinv[i] = gPa[(i >> 5) * 64 + 32 + (i & 31)];
    __syncthreads();

    // G = H^T H augmented -> invert
    for (int i = tid; i < 32 * 64; i += 128) {
        int r = i >> 6, c = i & 63;
        if (c < 32) {
            double s = 0.0;
            for (int m = 0; m < 64; ++m)
                s += (double)H[m * 32 + r] * (double)H[m * 32 + c];
            gGa[i] = s;
        } else {
            gGa[i] = (c - 32 == r) ? 1.0 : 0.0;
        }
    }
    __syncthreads();
    gj32(gGa);
    for (int i = tid; i < 1024; i += 128) gGinv[i] = gGa[(i >> 5) * 64 + 32 + (i & 31)];
    __syncthreads();

    // E = Pinv H^T ; Hinv = Ginv H^T   (both 32 x 64)
    for (int i = tid; i < 2048; i += 128) {
        int r = i >> 6, c = i & 63;
        double s = 0.0, s2 = 0.0;
        for (int k = 0; k < 32; ++k) {
            double h = (double)H[c * 32 + k];
            s  += gPinv[r * 32 + k] * h;
            s2 += gGinv[r * 32 + k] * h;
        }
        gE[i] = s;
        gHinvd[i] = s2;
    }
    __syncthreads();

    // D = H E  (64 x 64)
    for (int i = tid; i < 4096; i += 128) {
        int a = i >> 6, bc = i & 63;
        double s = 0.0;
        for (int k = 0; k < 32; ++k) s += (double)H[a * 32 + k] * gE[k * 64 + bc];
        gD[i] = s;
    }
    // C = E H = Pinv H^T H  (32 x 32)
    for (int i = tid; i < 1024; i += 128) {
        int r = i >> 5, c = i & 31;
        double s = 0.0;
        for (int m = 0; m < 64; ++m) s += gE[r * 64 + m] * (double)H[m * 32 + c];
        gCd[i] = s;
    }
    __syncthreads();

    // normalize C -> float
    {
        double loc = 0.0;
        for (int i = tid; i < 1024; i += 128) { double v = fabs(gCd[i]); if (v > loc) loc = v; }
        sred[tid] = loc;
        __syncthreads();
        if (tid == 0) { double m = 0; for (int i = 0; i < 128; ++i) if (sred[i] > m) m = sred[i]; sval[0] = m; }
        __syncthreads();
        double inv = 1.0 / sval[0];
        for (int i = tid; i < 1024; i += 128) gCf[0][i] = (float)(gCd[i] * inv);
        __syncthreads();
    }

    // 13 squarings with renormalization: C^(2^13), converges to rank-1 ~ u v^T
    int cur = 0;
    for (int s = 0; s < 13; ++s) {
        for (int i = tid; i < 1024; i += 128) {
            int r = i >> 5, c = i & 31;
            float acc = 0.0f;
            for (int k = 0; k < 32; ++k)
                acc = fmaf(gCf[cur][r * 32 + k], gCf[cur][k * 32 + c], acc);
            gCf[1 - cur][i] = acc;
        }
        __syncthreads();
        float lf = 0.0f;
        for (int i = tid; i < 1024; i += 128) { float v = fabsf(gCf[1 - cur][i]); if (v > lf) lf = v; }
        sred[tid] = (double)lf;
        __syncthreads();
        if (tid == 0) { double m = 0; for (int i = 0; i < 128; ++i) if (sred[i] > m) m = sred[i]; sval[0] = m; }
        __syncthreads();
        float inv = (float)(1.0 / sval[0]);
        for (int i = tid; i < 1024; i += 128) gCf[1 - cur][i] *= inv;
        cur = 1 - cur;
        __syncthreads();
    }

    // pick dominant column -> u (right eigvec of C); y = H u is top eigvec of D
    if (tid < 32) {
        float s = 0.0f;
        for (int i = 0; i < 32; ++i) { float v = gCf[cur][i * 32 + tid]; s = fmaf(v, v, s); }
        sred[tid] = (double)s;
    }
    __syncthreads();
    if (tid == 0) {
        int bj = 0; double bm = -1.0;
        for (int j = 0; j < 32; ++j) if (sred[j] > bm) { bm = sred[j]; bj = j; }
        sidx = bj;
    }
    __syncthreads();
    if (tid < 64) {
        double s = 0.0;
        for (int i = 0; i < 32; ++i) s += (double)H[tid * 32 + i] * (double)gCf[cur][i * 32 + sidx];
        gY[tid] = s;
    }
    __syncthreads();
    if (tid < 64) {
        double s = 0.0;
        for (int k = 0; k < 64; ++k) s += gD[tid * 64 + k] * gY[k];
        gZ[tid] = s;
    }
    __syncthreads();
    {
        double p1 = 0.0, p2 = 0.0;
        if (tid < 64) { p1 = gY[tid] * gZ[tid]; p2 = gY[tid] * gY[tid]; }
        sred[tid] = p1; __syncthreads();
        if (tid == 0) { double s = 0; for (int i = 0; i < 128; ++i) s += sred[i]; sval[1] = s; }
        __syncthreads();
        sred[tid] = p2; __syncthreads();
        if (tid == 0) {
            double s = 0; for (int i = 0; i < 128; ++i) s += sred[i];
            double lam = sval[1] / s;                  // Rayleigh: y^T D y / y^T y
            double t = (double)BETA / lam;
            gScalD[0] = t;
            gScalF[0] = (float)t;
        }
        __syncthreads();
    }

    // float exports
    for (int i = tid; i < 4096; i += 128) gDf[i] = (float)gD[i];
    for (int i = tid; i < 2048; i += 128) {
        int r = i >> 6, c = i & 63;
        gHinvf[r * 68 + c] = (float)gHinvd[i];
    }
}

// ----------------------------- per-row prep: mu, c, k=0 outputs -----------------------------
__global__ void prep_rows_kernel(const float* __restrict__ q, const float* __restrict__ b,
                                 const int* __restrict__ itp, float* __restrict__ out) {
    const int r = blockIdx.x;
    const int t = threadIdx.x;
    const size_t K = (size_t)(*itp) + 1;
    float* xs = out;
    float* ps = out + (size_t)BSZ * K * 128;
    const double tfac = gScalD[0];

    xs[((size_t)r * K) * 128 + t] = 0.0f;  // X0 = 0

    if (t < 64) {
        double s = 0.0;
        for (int i = 0; i < 32; ++i) s += (double)q[r * 32 + i] * gE[i * 64 + t];
        gMu[r * 64 + t] = (float)(tfac * (s - (double)b[r * 64 + t]));
    } else if (t < 96) {
        int i = t - 64;
        double s = 0.0;
        for (int k = 0; k < 64; ++k) s += gHinvd[i * 64 + k] * (double)b[r * 64 + k];
        gCvec[r * 32 + i] = (float)s;
        ps[((size_t)r * K) * 32 + i] = (float)(-s);   // primal at k=0: -Hinv b
    }
}

// ----------------------------- main persistent iteration kernel -----------------------------
// warp-per-row: 128 CTAs x 4 warps = 512 rows. D rows in registers (f32x2 packed).
__global__ void __launch_bounds__(128, 1)
iter_kernel(const int* __restrict__ itp, float* __restrict__ out) {
    const int iters = *itp;
    const size_t K = (size_t)iters + 1;
    float* xs_out = out;
    float* p_out  = out + (size_t)BSZ * K * 128;

    const int w = threadIdx.x >> 5;
    const int l = threadIdx.x & 31;
    const int r = blockIdx.x * 4 + w;

    __shared__ float Xs_[4][132];     // per-row state x[128]
    __shared__ float Ws_[4][64];      // per-row w = x1 D
    __shared__ float Hs[32 * 68];     // Hinv, padded rows

    for (int i = threadIdx.x; i < 32 * 68; i += 128) Hs[i] = gHinvf[i];

    // D rows l and l+32, packed as f32x2 pairs over k
    unsigned long long dlo[32], dhi[32];
#pragma unroll
    for (int kk = 0; kk < 32; ++kk) {
        dlo[kk] = *reinterpret_cast<const unsigned long long*>(&gDf[l * 64 + 2 * kk]);
        dhi[kk] = *reinterpret_cast<const unsigned long long*>(&gDf[(l + 32) * 64 + 2 * kk]);
    }

    const float tf  = gScalF[0];
    const float a2t = 2.0f * ALPHA * tf;
    const float c22 = 1.0f - a2t;
    float2 mu2 = *reinterpret_cast<const float2*>(&gMu[r * 64 + 2 * l]);
    float2 b2  = make_float2(-2.0f * ALPHA * mu2.x, -2.0f * ALPHA * mu2.y);
    const float cl = gCvec[r * 32 + l];

    float* X = Xs_[w];
    float* W = Ws_[w];
    *reinterpret_cast<float4*>(&X[4 * l]) = make_float4(0.f, 0.f, 0.f, 0.f);
    __syncthreads();   // Hs + X init

    float* xo = xs_out + (size_t)r * K * 128;
    float* po = p_out  + (size_t)r * K * 32;

    for (int k = 1; k <= iters; ++k) {
        // ---- w = x1 D : lane computes w[l], w[l+32], packed over k ----
        unsigned long long a0 = 0ull, a1 = 0ull, a2v = 0ull, a3 = 0ull;
#pragma unroll
        for (int q4 = 0; q4 < 16; ++q4) {
            ulonglong2 xv = *reinterpret_cast<ulonglong2*>(&X[4 * q4]);  // (x[4q],x[4q+1]),(x[4q+2],x[4q+3])
            a0  = ffma2(dlo[2 * q4],     xv.x, a0);
            a1  = ffma2(dlo[2 * q4 + 1], xv.y, a1);
            a2v = ffma2(dhi[2 * q4],     xv.x, a2v);
            a3  = ffma2(dhi[2 * q4 + 1], xv.y, a3);
        }
        W[l]      = hsum2(a0) + hsum2(a1);
        W[l + 32] = hsum2(a2v) + hsum2(a3);
        __syncwarp();

        // ---- elementwise update on own pair ----
        float2 wv  = *reinterpret_cast<float2*>(&W[2 * l]);
        float2 x1v = *reinterpret_cast<float2*>(&X[2 * l]);
        float2 x2v = *reinterpret_cast<float2*>(&X[64 + 2 * l]);
        float2 n1, n2;
        n1.x = fmaf(tf, wv.x + x2v.x, mu2.x);
        n1.y = fmaf(tf, wv.y + x2v.y, mu2.y);
        n2.x = fmaxf(fmaf(-a2t, wv.x, fmaf(c22, x2v.x, x1v.x)) + b2.x, 0.0f);
        n2.y = fmaxf(fmaf(-a2t, wv.y, fmaf(c22, x2v.y, x1v.y)) + b2.y, 0.0f);
        *reinterpret_cast<float2*>(&X[2 * l])      = n1;
        *reinterpret_cast<float2*>(&X[64 + 2 * l]) = n2;
        float* xok = xo + (size_t)k * 128;
        *reinterpret_cast<float2*>(&xok[2 * l])      = n1;
        *reinterpret_cast<float2*>(&xok[64 + 2 * l]) = n2;
        __syncwarp();

        // ---- primal: p[l] = Hinv[l,:] . x2' - c[l] ----
        unsigned long long p0 = 0ull, p1 = 0ull;
        const float* hr = &Hs[l * 68];
#pragma unroll
        for (int q4 = 0; q4 < 16; ++q4) {
            ulonglong2 xv = *reinterpret_cast<ulonglong2*>(&X[64 + 4 * q4]);
            ulonglong2 hv = *reinterpret_cast<const ulonglong2*>(&hr[4 * q4]);
            p0 = ffma2(hv.x, xv.x, p0);
            p1 = ffma2(hv.y, xv.y, p1);
        }
        po[(size_t)k * 32 + l] = (hsum2(p0) + hsum2(p1)) - cl;
    }
}

// ----------------------------- launch -----------------------------
extern "C" void kernel_launch(void* const* d_in, const int* in_sizes, int n_in,
                              void* d_out, int out_size) {
    (void)in_sizes; (void)out_size;
    const float* q = (const float*)d_in[0];
    const float* b = (const float*)d_in[1];
    const float* P = (const float*)d_in[2];
    const float* H = (const float*)d_in[3];

    const int* itp;
    if (n_in >= 5) {
        itp = (const int*)d_in[4];
    } else {
        void* p = nullptr;
        cudaGetSymbolAddress(&p, gItersDefault);
        itp = (const int*)p;
    }
    float* out = (float*)d_out;

    preproc_kernel<<<1, 128>>>(P, H);
    prep_rows_kernel<<<BSZ, 128>>>(q, b, itp, out);
    iter_kernel<<<128, 128>>>(itp, out);
}

// round 2
// speedup vs baseline: 2.0093x; 2.0093x over previous
#include <cuda_runtime.h>
#include <cstdint>

#define N32   32
#define M64   64
#define BSZ   512
#define ALPHA 1.0f
#define BETA  1.0f

// ----------------------------- device scratch (all fp32) -----------------------------
__device__ float fPa[32 * 64];       // GJ augmented for P
__device__ float fGa[32 * 64];       // GJ augmented for G = H^T H
__device__ float fPinv[32 * 32];
__device__ float fGinv[32 * 32];
__device__ float fE[32 * 64];        // E = Pinv H^T
__device__ float fHinv[32 * 64];     // Hinv = Ginv H^T
__device__ float gDf[64 * 64];       // D = H Pinv H^T
__device__ float gHinvf[32 * 68];    // Hinv padded stride 68 (16B-aligned rows)
__device__ float gScalF[4];
__device__ float gMu[BSZ * 64];
__device__ float gCvec[BSZ * 32];
__device__ int   gItersDefault = 1000;

// ----------------------------- helpers -----------------------------
__device__ __forceinline__ unsigned long long ffma2(unsigned long long a,
                                                    unsigned long long b,
                                                    unsigned long long c) {
    unsigned long long d;
    asm("fma.rn.f32x2 %0, %1, %2, %3;" : "=l"(d) : "l"(a), "l"(b), "l"(c));
    return d;
}
__device__ __forceinline__ float hsum2(unsigned long long a) {
    float lo, hi;
    asm("mov.b64 {%0, %1}, %2;" : "=f"(lo), "=f"(hi) : "l"(a));
    return lo + hi;
}
__device__ __forceinline__ float warpMax(float v) {
#pragma unroll
    for (int o = 16; o; o >>= 1) v = fmaxf(v, __shfl_xor_sync(0xffffffffu, v, o));
    return v;
}
__device__ __forceinline__ float warpSum(float v) {
#pragma unroll
    for (int o = 16; o; o >>= 1) v += __shfl_xor_sync(0xffffffffu, v, o);
    return v;
}
__device__ __forceinline__ float blockMax128(float v, float* sred4) {
    v = warpMax(v);
    if ((threadIdx.x & 31) == 0) sred4[threadIdx.x >> 5] = v;
    __syncthreads();
    v = fmaxf(fmaxf(sred4[0], sred4[1]), fmaxf(sred4[2], sred4[3]));
    __syncthreads();
    return v;
}
__device__ __forceinline__ float blockSum128(float v, float* sred4) {
    v = warpSum(v);
    if ((threadIdx.x & 31) == 0) sred4[threadIdx.x >> 5] = v;
    __syncthreads();
    v = (sred4[0] + sred4[1]) + (sred4[2] + sred4[3]);
    __syncthreads();
    return v;
}

// Gauss-Jordan on [32 x 64] augmented matrix, 128 threads, fp32.
__device__ void gjf(float* Aug) {
    const int tid = threadIdx.x;
    for (int p = 0; p < 32; ++p) {
        __syncthreads();
        float pv = Aug[p * 64 + p];
        __syncthreads();
        float ipv = 1.0f / pv;
        if (tid < 64) Aug[p * 64 + tid] *= ipv;
        __syncthreads();
        int r  = tid >> 2;
        int cs = (tid & 3) * 16;
        float f = Aug[r * 64 + p];
        __syncthreads();
        if (r != p) {
#pragma unroll
            for (int c = 0; c < 16; ++c)
                Aug[r * 64 + cs + c] = fmaf(-f, Aug[p * 64 + cs + c], Aug[r * 64 + cs + c]);
        }
    }
    __syncthreads();
}

// ----------------------------- preprocessing (1 CTA, fp32) -----------------------------
__global__ void preproc_kernel(const float* __restrict__ P, const float* __restrict__ H) {
    const int tid = threadIdx.x;
    __shared__ float sred4[4];
    __shared__ float sC[2][1024];
    __shared__ float sy[64], sz[64];
    __shared__ int sidx;

    // Build augmented P and G = H^T H
    for (int i = tid; i < 2048; i += 128) {
        int r = i >> 6, c = i & 63;
        fPa[i] = (c < 32) ? P[r * 32 + c] : ((c - 32 == r) ? 1.0f : 0.0f);
    }
    for (int i = tid; i < 2048; i += 128) {
        int r = i >> 6, c = i & 63;
        if (c < 32) {
            float s0 = 0.0f, s1 = 0.0f;
            for (int m = 0; m < 64; m += 2) {
                s0 = fmaf(H[m * 32 + r], H[m * 32 + c], s0);
                s1 = fmaf(H[(m + 1) * 32 + r], H[(m + 1) * 32 + c], s1);
            }
            fGa[i] = s0 + s1;
        } else {
            fGa[i] = (c - 32 == r) ? 1.0f : 0.0f;
        }
    }
    __syncthreads();
    gjf(fPa);
    gjf(fGa);
    for (int i = tid; i < 1024; i += 128) {
        fPinv[i] = fPa[(i >> 5) * 64 + 32 + (i & 31)];
        fGinv[i] = fGa[(i >> 5) * 64 + 32 + (i & 31)];
    }
    __syncthreads();

    // E = Pinv H^T ; Hinv = Ginv H^T  (32 x 64 each)
    for (int i = tid; i < 2048; i += 128) {
        int r = i >> 6, c = i & 63;
        float s = 0.0f, s2 = 0.0f;
#pragma unroll 8
        for (int k = 0; k < 32; ++k) {
            float h = H[c * 32 + k];
            s  = fmaf(fPinv[r * 32 + k], h, s);
            s2 = fmaf(fGinv[r * 32 + k], h, s2);
        }
        fE[i] = s;
        fHinv[i] = s2;
        gHinvf[r * 68 + c] = s2;
    }
    __syncthreads();

    // D = H E (64x64) into gDf ; C = E H (32x32) into sC[0]
    for (int i = tid; i < 4096; i += 128) {
        int a = i >> 6, c = i & 63;
        float s0 = 0.0f, s1 = 0.0f;
        for (int k = 0; k < 32; k += 2) {
            s0 = fmaf(H[a * 32 + k],     fE[k * 64 + c],       s0);
            s1 = fmaf(H[a * 32 + k + 1], fE[(k + 1) * 64 + c], s1);
        }
        gDf[i] = s0 + s1;
    }
    for (int i = tid; i < 1024; i += 128) {
        int r = i >> 5, c = i & 31;
        float s0 = 0.0f, s1 = 0.0f;
        for (int m = 0; m < 64; m += 2) {
            s0 = fmaf(fE[r * 64 + m],     H[m * 32 + c],       s0);
            s1 = fmaf(fE[r * 64 + m + 1], H[(m + 1) * 32 + c], s1);
        }
        sC[0][i] = s0 + s1;
    }
    __syncthreads();

    // Normalize C
    {
        float loc = 0.0f;
        for (int i = tid; i < 1024; i += 128) loc = fmaxf(loc, fabsf(sC[0][i]));
        float m = blockMax128(loc, sred4);
        float inv = 1.0f / m;
        for (int i = tid; i < 1024; i += 128) sC[0][i] *= inv;
        __syncthreads();
    }

    // 13 squarings with renormalization -> C^(2^13) ~ rank-1 u v^T
    int cur = 0;
    const int r8 = tid >> 2, c8 = (tid & 3) << 3;
    for (int s = 0; s < 13; ++s) {
        float acc[8] = {0, 0, 0, 0, 0, 0, 0, 0};
        for (int k = 0; k < 32; ++k) {
            float a = sC[cur][r8 * 32 + k];
#pragma unroll
            for (int j = 0; j < 8; ++j)
                acc[j] = fmaf(a, sC[cur][k * 32 + c8 + j], acc[j]);
        }
        float loc = 0.0f;
#pragma unroll
        for (int j = 0; j < 8; ++j) loc = fmaxf(loc, fabsf(acc[j]));
        float m = blockMax128(loc, sred4);   // contains syncthreads (reads done)
        float inv = 1.0f / m;
#pragma unroll
        for (int j = 0; j < 8; ++j) sC[1 - cur][r8 * 32 + c8 + j] = acc[j] * inv;
        __syncthreads();
        cur ^= 1;
    }

    // Dominant column -> u ; y = H u is top eigvec of D
    if (tid < 32) {
        float s = 0.0f;
        for (int i = 0; i < 32; ++i) { float v = sC[cur][i * 32 + tid]; s = fmaf(v, v, s); }
        sy[tid] = s;
    }
    __syncthreads();
    if (tid == 0) {
        int bj = 0; float bm = -1.0f;
        for (int j = 0; j < 32; ++j) if (sy[j] > bm) { bm = sy[j]; bj = j; }
        sidx = bj;
    }
    __syncthreads();
    if (tid < 64) {
        float s = 0.0f;
        for (int i = 0; i < 32; ++i) s = fmaf(H[tid * 32 + i], sC[cur][i * 32 + sidx], s);
        sy[tid] = s;
    }
    __syncthreads();
    if (tid < 64) {
        float s = 0.0f;
        for (int k = 0; k < 64; ++k) s = fmaf(gDf[tid * 64 + k], sy[k], s);
        sz[tid] = s;
    }
    __syncthreads();
    float p1 = (tid < 64) ? sy[tid] * sz[tid] : 0.0f;
    float p2 = (tid < 64) ? sy[tid] * sy[tid] : 0.0f;
    float num = blockSum128(p1, sred4);   // y.Dy
    float den = blockSum128(p2, sred4);   // y.y
    if (tid == 0) gScalF[0] = BETA * den / num;   // t = beta / lambda_max
}

// ----------------------------- per-row prep: mu, c, k=0 X row -----------------------------
__global__ void prep_rows_kernel(const float* __restrict__ q, const float* __restrict__ b,
                                 const int* __restrict__ itp, float* __restrict__ out) {
    const int r = blockIdx.x;
    const int t = threadIdx.x;
    const size_t K = (size_t)(*itp) + 1;

    out[((size_t)r * K) * 128 + t] = 0.0f;   // X0 = 0

    const float tf = gScalF[0];
    if (t < 64) {
        float s = 0.0f;
#pragma unroll 8
        for (int i = 0; i < 32; ++i) s = fmaf(q[r * 32 + i], fE[i * 64 + t], s);
        gMu[r * 64 + t] = tf * (s - b[r * 64 + t]);
    } else if (t < 96) {
        int i = t - 64;
        float s = 0.0f;
#pragma unroll 8
        for (int k = 0; k < 64; ++k) s = fmaf(fHinv[i * 64 + k], b[r * 64 + k], s);
        gCvec[r * 32 + i] = s;
    }
}

// ----------------------------- main persistent iteration kernel -----------------------------
// warp-per-row: 128 CTAs x 4 warps = 512 rows.
// Lane l owns D rows 2l,2l+1 (outputs land on the pair the lane updates) and Hinv row l.
// Primal GEMV of iteration k-1 pipelined into body k (6 interleaved FFMA2 chains).
__global__ void __launch_bounds__(128, 1)
iter_kernel(const int* __restrict__ itp, float* __restrict__ out) {
    const int iters = *itp;
    const size_t K = (size_t)iters + 1;
    float* xs_out = out;
    float* p_out  = out + (size_t)BSZ * K * 128;

    const int w = threadIdx.x >> 5;
    const int l = threadIdx.x & 31;
    const int r = blockIdx.x * 4 + w;

    __shared__ __align__(16) float Xb[2][4][132];    // ping-pong X per warp
    __shared__ __align__(16) float Hs[32 * 68];      // Hinv, padded rows

    for (int i = threadIdx.x; i < 32 * 68; i += 128) Hs[i] = gHinvf[i];

    // D rows 2l and 2l+1, packed f32x2 over k
    unsigned long long d0[32], d1[32];
#pragma unroll
    for (int kk = 0; kk < 32; ++kk) {
        d0[kk] = *reinterpret_cast<const unsigned long long*>(&gDf[(2 * l)     * 64 + 2 * kk]);
        d1[kk] = *reinterpret_cast<const unsigned long long*>(&gDf[(2 * l + 1) * 64 + 2 * kk]);
    }

    const float tf  = gScalF[0];
    const float a2t = 2.0f * ALPHA * tf;
    const float c22 = 1.0f - a2t;
    float2 mu2 = *reinterpret_cast<const float2*>(&gMu[r * 64 + 2 * l]);
    float2 b2  = make_float2(-2.0f * ALPHA * mu2.x, -2.0f * ALPHA * mu2.y);
    const float cl = gCvec[r * 32 + l];
    const float* hr = &Hs[l * 68];

    *reinterpret_cast<float4*>(&Xb[0][w][4 * l]) = make_float4(0.f, 0.f, 0.f, 0.f);
    __syncthreads();   // Hs + X init visible

    float* xo = xs_out + (size_t)r * K * 128;
    float* po = p_out  + (size_t)r * K * 32;

    for (int k = 1; k <= iters; ++k) {
        float* Xr = Xb[(k - 1) & 1][w];
        float* Xw = Xb[k & 1][w];

        unsigned long long a0 = 0ull, a1 = 0ull, a2v = 0ull, a3 = 0ull;
        unsigned long long p0 = 0ull, p1 = 0ull;
#pragma unroll
        for (int q4 = 0; q4 < 16; ++q4) {
            ulonglong2 xv = *reinterpret_cast<ulonglong2*>(&Xr[4 * q4]);        // x1 pairs
            ulonglong2 yv = *reinterpret_cast<ulonglong2*>(&Xr[64 + 4 * q4]);   // x2 pairs
            ulonglong2 hv = *reinterpret_cast<const ulonglong2*>(&hr[4 * q4]);  // Hinv pairs
            a0  = ffma2(d0[2 * q4],     xv.x, a0);
            a1  = ffma2(d0[2 * q4 + 1], xv.y, a1);
            a2v = ffma2(d1[2 * q4],     xv.x, a2v);
            a3  = ffma2(d1[2 * q4 + 1], xv.y, a3);
            p0  = ffma2(hv.x, yv.x, p0);
            p1  = ffma2(hv.y, yv.y, p1);
        }
        float w0 = hsum2(a0)  + hsum2(a1);    // w[2l]
        float w1 = hsum2(a2v) + hsum2(a3);    // w[2l+1]
        float pv = (hsum2(p0) + hsum2(p1)) - cl;   // primal_{k-1}[l]

        float2 x1p = *reinterpret_cast<float2*>(&Xr[2 * l]);
        float2 x2p = *reinterpret_cast<float2*>(&Xr[64 + 2 * l]);
        float2 n1, n2;
        n1.x = fmaf(tf, w0 + x2p.x, mu2.x);
        n1.y = fmaf(tf, w1 + x2p.y, mu2.y);
        n2.x = fmaxf(fmaf(-a2t, w0, fmaf(c22, x2p.x, x1p.x)) + b2.x, 0.0f);
        n2.y = fmaxf(fmaf(-a2t, w1, fmaf(c22, x2p.y, x1p.y)) + b2.y, 0.0f);

        *reinterpret_cast<float2*>(&Xw[2 * l])      = n1;
        *reinterpret_cast<float2*>(&Xw[64 + 2 * l]) = n2;

        float* xok = xo + (size_t)k * 128;
        __stcs(reinterpret_cast<float2*>(&xok[2 * l]),      n1);
        __stcs(reinterpret_cast<float2*>(&xok[64 + 2 * l]), n2);
        __stcs(&po[(size_t)(k - 1) * 32 + l], pv);

        __syncwarp();   // publish X_k (reads of X_{k-1} were from the other buffer)
    }

    // final primal for k = iters
    {
        float* Xr = Xb[iters & 1][w];
        unsigned long long p0 = 0ull, p1 = 0ull;
#pragma unroll
        for (int q4 = 0; q4 < 16; ++q4) {
            ulonglong2 yv = *reinterpret_cast<ulonglong2*>(&Xr[64 + 4 * q4]);
            ulonglong2 hv = *reinterpret_cast<const ulonglong2*>(&hr[4 * q4]);
            p0 = ffma2(hv.x, yv.x, p0);
            p1 = ffma2(hv.y, yv.y, p1);
        }
        __stcs(&po[(size_t)iters * 32 + l], (hsum2(p0) + hsum2(p1)) - cl);
    }
}

// ----------------------------- launch -----------------------------
extern "C" void kernel_launch(void* const* d_in, const int* in_sizes, int n_in,
                              void* d_out, int out_size) {
    (void)in_sizes; (void)out_size;
    const float* q = (const float*)d_in[0];
    const float* b = (const float*)d_in[1];
    const float* P = (const float*)d_in[2];
    const float* H = (const float*)d_in[3];

    const int* itp;
    if (n_in >= 5) {
        itp = (const int*)d_in[4];
    } else {
        void* p = nullptr;
        cudaGetSymbolAddress(&p, gItersDefault);
        itp = (const int*)p;
    }
    float* out = (float*)d_out;

    preproc_kernel<<<1, 128>>>(P, H);
    prep_rows_kernel<<<BSZ, 128>>>(q, b, itp, out);
    iter_kernel<<<128, 128>>>(itp, out);
}

// round 3
// speedup vs baseline: 2.0478x; 1.0192x over previous
#include <cuda_runtime.h>
#include <cstdint>

#define N32   32
#define M64   64
#define BSZ   512
#define ALPHA 1.0f
#define BETA  1.0f

// ----------------------------- device exports from preproc -----------------------------
__device__ float gDf[64 * 64];       // D = H Pinv H^T
__device__ float gHinv[32 * 64];     // Hinv = (H^T H)^-1 H^T
__device__ float gE[32 * 64];        // E = Pinv H^T  (for mu)
__device__ float gScalF[4];
__device__ int   gItersDefault = 1000;

// ----------------------------- helpers -----------------------------
__device__ __forceinline__ unsigned long long ffma2(unsigned long long a,
                                                    unsigned long long b,
                                                    unsigned long long c) {
    unsigned long long d;
    asm("fma.rn.f32x2 %0, %1, %2, %3;" : "=l"(d) : "l"(a), "l"(b), "l"(c));
    return d;
}
__device__ __forceinline__ float hsum2(unsigned long long a) {
    float lo, hi;
    asm("mov.b64 {%0, %1}, %2;" : "=f"(lo), "=f"(hi) : "l"(a));
    return lo + hi;
}
__device__ __forceinline__ float warpMax(float v) {
#pragma unroll
    for (int o = 16; o; o >>= 1) v = fmaxf(v, __shfl_xor_sync(0xffffffffu, v, o));
    return v;
}
__device__ __forceinline__ float warpSum(float v) {
#pragma unroll
    for (int o = 16; o; o >>= 1) v += __shfl_xor_sync(0xffffffffu, v, o);
    return v;
}
__device__ __forceinline__ float blockMax128(float v, float* sred4) {
    v = warpMax(v);
    if ((threadIdx.x & 31) == 0) sred4[threadIdx.x >> 5] = v;
    __syncthreads();
    v = fmaxf(fmaxf(sred4[0], sred4[1]), fmaxf(sred4[2], sred4[3]));
    __syncthreads();
    return v;
}
__device__ __forceinline__ float blockSum128(float v, float* sred4) {
    v = warpSum(v);
    if ((threadIdx.x & 31) == 0) sred4[threadIdx.x >> 5] = v;
    __syncthreads();
    v = (sred4[0] + sred4[1]) + (sred4[2] + sred4[3]);
    __syncthreads();
    return v;
}

// Gauss-Jordan on [32 x 64] augmented matrix in SHARED memory, 128 threads.
__device__ void gjf_sm(float* Aug) {
    const int tid = threadIdx.x;
    for (int p = 0; p < 32; ++p) {
        __syncthreads();
        float pv = Aug[p * 64 + p];
        __syncthreads();
        float ipv = 1.0f / pv;
        if (tid < 64) Aug[p * 64 + tid] *= ipv;
        __syncthreads();
        int r  = tid >> 2;
        int cs = (tid & 3) * 16;
        float f = Aug[r * 64 + p];
        __syncthreads();
        if (r != p) {
#pragma unroll
            for (int c = 0; c < 16; ++c)
                Aug[r * 64 + cs + c] = fmaf(-f, Aug[p * 64 + cs + c], Aug[r * 64 + cs + c]);
        }
    }
    __syncthreads();
}

// ----------------------------- preprocessing (1 CTA, fp32, all-smem) -----------------------------
__global__ void preproc_kernel(const float* __restrict__ P, const float* __restrict__ H) {
    const int tid = threadIdx.x;
    __shared__ float sA[2048];                    // GJ workspace; later reused as C buffers
    __shared__ float sPinv[1024], sGinv[1024];
    __shared__ float sE[2048];
    __shared__ float sD[4096];
    __shared__ float sred4[4];
    __shared__ float sy[64], sz[64];
    __shared__ int sidx;

    // ---- invert P ----
    for (int i = tid; i < 2048; i += 128) {
        int r = i >> 6, c = i & 63;
        sA[i] = (c < 32) ? P[r * 32 + c] : ((c - 32 == r) ? 1.0f : 0.0f);
    }
    __syncthreads();
    gjf_sm(sA);
    for (int i = tid; i < 1024; i += 128) sPinv[i] = sA[(i >> 5) * 64 + 32 + (i & 31)];
    __syncthreads();

    // ---- invert G = H^T H ----
    for (int i = tid; i < 2048; i += 128) {
        int r = i >> 6, c = i & 63;
        if (c < 32) {
            float s0 = 0.0f, s1 = 0.0f;
            for (int m = 0; m < 64; m += 2) {
                s0 = fmaf(H[m * 32 + r],       H[m * 32 + c],       s0);
                s1 = fmaf(H[(m + 1) * 32 + r], H[(m + 1) * 32 + c], s1);
            }
            sA[i] = s0 + s1;
        } else {
            sA[i] = (c - 32 == r) ? 1.0f : 0.0f;
        }
    }
    __syncthreads();
    gjf_sm(sA);
    for (int i = tid; i < 1024; i += 128) sGinv[i] = sA[(i >> 5) * 64 + 32 + (i & 31)];
    __syncthreads();

    // ---- E = Pinv H^T (smem+gmem) ; Hinv = Ginv H^T (gmem only) ----
    for (int i = tid; i < 2048; i += 128) {
        int r = i >> 6, c = i & 63;
        float s = 0.0f, s2 = 0.0f;
#pragma unroll 8
        for (int k = 0; k < 32; ++k) {
            float h = H[c * 32 + k];
            s  = fmaf(sPinv[r * 32 + k], h, s);
            s2 = fmaf(sGinv[r * 32 + k], h, s2);
        }
        sE[i] = s;
        gE[i] = s;
        gHinv[i] = s2;
    }
    __syncthreads();

    // ---- D = H E (64x64) ; C = E H (32x32, into sA) ----
    for (int i = tid; i < 4096; i += 128) {
        int a = i >> 6, c = i & 63;
        float s0 = 0.0f, s1 = 0.0f;
        for (int k = 0; k < 32; k += 2) {
            s0 = fmaf(H[a * 32 + k],     sE[k * 64 + c],       s0);
            s1 = fmaf(H[a * 32 + k + 1], sE[(k + 1) * 64 + c], s1);
        }
        sD[i] = s0 + s1;
        gDf[i] = s0 + s1;
    }
    float* sC0 = sA;
    float* sC1 = sA + 1024;
    for (int i = tid; i < 1024; i += 128) {
        int r = i >> 5, c = i & 31;
        float s0 = 0.0f, s1 = 0.0f;
        for (int m = 0; m < 64; m += 2) {
            s0 = fmaf(sE[r * 64 + m],     H[m * 32 + c],       s0);
            s1 = fmaf(sE[r * 64 + m + 1], H[(m + 1) * 32 + c], s1);
        }
        sC0[i] = s0 + s1;
    }
    __syncthreads();

    // ---- normalize C ----
    {
        float loc = 0.0f;
        for (int i = tid; i < 1024; i += 128) loc = fmaxf(loc, fabsf(sC0[i]));
        float m = blockMax128(loc, sred4);
        float inv = 1.0f / m;
        for (int i = tid; i < 1024; i += 128) sC0[i] *= inv;
        __syncthreads();
    }

    // ---- 13 squarings with renorm -> C^(2^13) ~ rank-1 ----
    const int r8 = tid >> 2, c8 = (tid & 3) << 3;
    float* cur = sC0;
    float* nxt = sC1;
    for (int s = 0; s < 13; ++s) {
        float acc[8] = {0, 0, 0, 0, 0, 0, 0, 0};
        for (int k = 0; k < 32; ++k) {
            float a = cur[r8 * 32 + k];
#pragma unroll
            for (int j = 0; j < 8; ++j)
                acc[j] = fmaf(a, cur[k * 32 + c8 + j], acc[j]);
        }
        float loc = 0.0f;
#pragma unroll
        for (int j = 0; j < 8; ++j) loc = fmaxf(loc, fabsf(acc[j]));
        float m = blockMax128(loc, sred4);
        float inv = 1.0f / m;
#pragma unroll
        for (int j = 0; j < 8; ++j) nxt[r8 * 32 + c8 + j] = acc[j] * inv;
        __syncthreads();
        float* t = cur; cur = nxt; nxt = t;
    }

    // ---- dominant column u; y = H u top eigvec of D; Rayleigh ----
    if (tid < 32) {
        float s = 0.0f;
        for (int i = 0; i < 32; ++i) { float v = cur[i * 32 + tid]; s = fmaf(v, v, s); }
        sy[tid] = s;
    }
    __syncthreads();
    if (tid == 0) {
        int bj = 0; float bm = -1.0f;
        for (int j = 0; j < 32; ++j) if (sy[j] > bm) { bm = sy[j]; bj = j; }
        sidx = bj;
    }
    __syncthreads();
    if (tid < 64) {
        float s = 0.0f;
        for (int i = 0; i < 32; ++i) s = fmaf(H[tid * 32 + i], cur[i * 32 + sidx], s);
        sy[tid] = s;
    }
    __syncthreads();
    if (tid < 64) {
        float s = 0.0f;
        for (int k = 0; k < 64; ++k) s = fmaf(sD[tid * 64 + k], sy[k], s);
        sz[tid] = s;
    }
    __syncthreads();
    float p1 = (tid < 64) ? sy[tid] * sz[tid] : 0.0f;
    float p2 = (tid < 64) ? sy[tid] * sy[tid] : 0.0f;
    float num = blockSum128(p1, sred4);   // y.Dy
    float den = blockSum128(p2, sred4);   // y.y
    if (tid == 0) gScalF[0] = BETA * den / num;   // t = beta / lambda_max
}

// ----------------------------- main persistent iteration kernel -----------------------------
// 128 CTAs x 256 threads. Row s (s=0..3) handled by warp pair {s, s+4} (both on SMSP s).
// Lane owns one column j = t*32+l: D row j (32 x u64) and half an Hinv row in registers.
// Own x1[j], x2[j] carried in registers; partner halves read from smem ping-pong.
// Primal of iter k-1 fused into iter k; pair synced with a 64-thread named barrier.
__global__ void __launch_bounds__(256, 1)
iter_kernel(const int* __restrict__ itp,
            const float* __restrict__ q, const float* __restrict__ b,
            float* __restrict__ out) {
    const int iters = *itp;
    const size_t K = (size_t)iters + 1;

    const int wid = threadIdx.x >> 5;
    const int l   = threadIdx.x & 31;
    const int s   = wid & 3;          // row slot in CTA (also SMSP)
    const int t   = wid >> 2;         // half: 0 or 1
    const int j   = t * 32 + l;       // owned column
    const int r   = blockIdx.x * 4 + s;
    const int barid = s + 1;

    __shared__ __align__(16) float Xb[2][4][132];   // ping-pong x[128] per row

    // ---- registers: D row j, Hinv half-row ----
    unsigned long long d[32];
#pragma unroll
    for (int kk = 0; kk < 32; ++kk)
        d[kk] = *reinterpret_cast<const unsigned long long*>(&gDf[j * 64 + 2 * kk]);

    const int ip = t * 16 + (l >> 1);   // primal output index
    const int h  = l & 1;               // k-half of the dot
    unsigned long long hreg[16];
#pragma unroll
    for (int m = 0; m < 16; ++m)
        hreg[m] = *reinterpret_cast<const unsigned long long*>(&gHinv[ip * 64 + h * 32 + 2 * m]);

    // ---- scalars: mu_j, c_i ----
    const float tf  = gScalF[0];
    const float a2t = 2.0f * ALPHA * tf;
    const float c22 = 1.0f - a2t;

    float mu;
    {
        float acc = 0.0f;
#pragma unroll 8
        for (int i = 0; i < 32; ++i) acc = fmaf(q[r * 32 + i], gE[i * 64 + j], acc);
        mu = tf * (acc - b[r * 64 + j]);
    }
    const float bterm = -2.0f * ALPHA * mu;

    float cl;
    {
        unsigned long long c0 = 0ull, c1 = 0ull;
#pragma unroll
        for (int m = 0; m < 8; ++m) {
            ulonglong2 bv = *reinterpret_cast<const ulonglong2*>(&b[r * 64 + h * 32 + 4 * m]);
            c0 = ffma2(hreg[2 * m],     bv.x, c0);
            c1 = ffma2(hreg[2 * m + 1], bv.y, c1);
        }
        float part = hsum2(c0) + hsum2(c1);
        cl = part + __shfl_xor_sync(0xffffffffu, part, 1);
    }

    float* xo = out + (size_t)r * K * 128;
    float* po = out + (size_t)BSZ * K * 128 + (size_t)r * K * 32;

    // ---- k = 0 outputs + state init ----
    float x1o = 0.0f, x2o = 0.0f;
    Xb[0][s][j] = 0.0f;
    Xb[0][s][64 + j] = 0.0f;
    xo[j] = 0.0f;
    xo[64 + j] = 0.0f;
    asm volatile("bar.sync %0, %1;" :: "r"(barid), "r"(64) : "memory");

    for (int k = 1; k <= iters; ++k) {
        float* Xr = Xb[(k - 1) & 1][s];
        float* Xw = Xb[k & 1][s];

        // matvec: w[j] = D[j,:] . x1   (x1 = Xr[0:64], broadcast loads)
        unsigned long long a0 = 0ull, a1 = 0ull;
        // primal (k-1): dot over x2 half  (x2 = Xr[64:128])
        unsigned long long p0 = 0ull, p1 = 0ull;
#pragma unroll
        for (int q4 = 0; q4 < 8; ++q4) {
            ulonglong2 xv = *reinterpret_cast<ulonglong2*>(&Xr[8 * q4]);
            ulonglong2 xw = *reinterpret_cast<ulonglong2*>(&Xr[8 * q4 + 4]);
            ulonglong2 yv = *reinterpret_cast<ulonglong2*>(&Xr[64 + h * 32 + 4 * q4]);
            a0 = ffma2(d[4 * q4],     xv.x, a0);
            a1 = ffma2(d[4 * q4 + 1], xv.y, a1);
            a0 = ffma2(d[4 * q4 + 2], xw.x, a0);
            a1 = ffma2(d[4 * q4 + 3], xw.y, a1);
            p0 = ffma2(hreg[2 * q4],     yv.x, p0);
            p1 = ffma2(hreg[2 * q4 + 1], yv.y, p1);
        }
        float wj = hsum2(a0) + hsum2(a1);
        float part = hsum2(p0) + hsum2(p1);
        float pv = part + __shfl_xor_sync(0xffffffffu, part, 1) - cl;
        if (h == 0) __stcs(&po[(size_t)(k - 1) * 32 + ip], pv);

        // elementwise update (own column, register-resident state)
        float n1 = fmaf(tf, wj + x2o, mu);
        float n2 = fmaxf(fmaf(-a2t, wj, fmaf(c22, x2o, x1o)) + bterm, 0.0f);
        x1o = n1; x2o = n2;

        Xw[j] = n1;
        Xw[64 + j] = n2;
        float* xok = xo + (size_t)k * 128;
        __stcs(&xok[j], n1);
        __stcs(&xok[64 + j], n2);

        asm volatile("bar.sync %0, %1;" :: "r"(barid), "r"(64) : "memory");
    }

    // final primal (k = iters)
    {
        float* Xr = Xb[iters & 1][s];
        unsigned long long p0 = 0ull, p1 = 0ull;
#pragma unroll
        for (int q4 = 0; q4 < 8; ++q4) {
            ulonglong2 yv = *reinterpret_cast<ulonglong2*>(&Xr[64 + h * 32 + 4 * q4]);
            p0 = ffma2(hreg[2 * q4],     yv.x, p0);
            p1 = ffma2(hreg[2 * q4 + 1], yv.y, p1);
        }
        float part = hsum2(p0) + hsum2(p1);
        float pv = part + __shfl_xor_sync(0xffffffffu, part, 1) - cl;
        if (h == 0) __stcs(&po[(size_t)iters * 32 + ip], pv);
    }
}

// ----------------------------- launch -----------------------------
extern "C" void kernel_launch(void* const* d_in, const int* in_sizes, int n_in,
                              void* d_out, int out_size) {
    (void)in_sizes; (void)out_size;
    const float* q = (const float*)d_in[0];
    const float* b = (const float*)d_in[1];
    const float* P = (const float*)d_in[2];
    const float* H = (const float*)d_in[3];

    const int* itp;
    if (n_in >= 5) {
        itp = (const int*)d_in[4];
    } else {
        void* p = nullptr;
        cudaGetSymbolAddress(&p, gItersDefault);
        itp = (const int*)p;
    }
    float* out = (float*)d_out;

    preproc_kernel<<<1, 128>>>(P, H);
    iter_kernel<<<128, 256>>>(itp, q, b, out);
}

// round 5
// speedup vs baseline: 2.2075x; 1.0780x over previous
#include <cuda_runtime.h>
#include <cstdint>

#define N32   32
#define M64   64
#define BSZ   512
#define ALPHA 1.0f
#define BETA  1.0f

__device__ int gItersDefault = 1000;

// ----------------------------- helpers -----------------------------
__device__ __forceinline__ unsigned long long ffma2(unsigned long long a,
                                                    unsigned long long b,
                                                    unsigned long long c) {
    unsigned long long d;
    asm("fma.rn.f32x2 %0, %1, %2, %3;" : "=l"(d) : "l"(a), "l"(b), "l"(c));
    return d;
}
__device__ __forceinline__ float hsum2(unsigned long long a) {
    float lo, hi;
    asm("mov.b64 {%0, %1}, %2;" : "=f"(lo), "=f"(hi) : "l"(a));
    return lo + hi;
}
__device__ __forceinline__ float warpMax(float v) {
#pragma unroll
    for (int o = 16; o; o >>= 1) v = fmaxf(v, __shfl_xor_sync(0xffffffffu, v, o));
    return v;
}
__device__ __forceinline__ float warpSum(float v) {
#pragma unroll
    for (int o = 16; o; o >>= 1) v += __shfl_xor_sync(0xffffffffu, v, o);
    return v;
}

// ----------------------------- fused kernel -----------------------------
// grid = 128 CTAs x 128 threads. Phase 1: every CTA redundantly does the full
// preprocessing in its own smem (avoids the single-CTA issue throttle).
// Phase 2: warp-per-row iteration (4 rows per CTA), warp-synchronous only.
//
// Shared buffer reuse plan (floats):
//   w0 [0:2048)       GJ workspace / C squaring buffers / later X ping-pong
//   w1 [2048:3072)    Pinv, later Ginv
//   w2 [3072:5120)    E = Pinv H^T           (persists into prologue: mu)
//   w3 [5120:9216)    D = H Pinv H^T         (persists: register load)
//   w4 [9216:11392)   Hinv stride-68         (persists: whole run)
__global__ void __launch_bounds__(128, 1)
qp_fused_kernel(const int* __restrict__ itp,
                const float* __restrict__ q, const float* __restrict__ b,
                const float* __restrict__ P, const float* __restrict__ H,
                float* __restrict__ out) {
    __shared__ __align__(16) float buf[11392];
    __shared__ float sred4[4];
    __shared__ float sy[64], sz[64];
    __shared__ float sTf;
    __shared__ int sidx;

    float* w0 = buf;
    float* w1 = buf + 2048;
    float* w2 = buf + 3072;
    float* w3 = buf + 5120;
    float* w4 = buf + 9216;

    const int tid = threadIdx.x;

    // ================= PHASE 1: preprocessing (redundant per CTA) =================
    // ---- stage 1: invert P (Gauss-Jordan on [P|I]) ----
    for (int i = tid; i < 2048; i += 128) {
        int r = i >> 6, c = i & 63;
        w0[i] = (c < 32) ? P[r * 32 + c] : ((c - 32 == r) ? 1.0f : 0.0f);
    }
    __syncthreads();
    for (int p = 0; p < 32; ++p) {
        float pv = w0[p * 64 + p];
        float ipv = 1.0f / pv;
        __syncthreads();
        if (tid < 64) w0[p * 64 + tid] *= ipv;
        __syncthreads();
        int rr = tid >> 2, cs = (tid & 3) * 16;
        float f = w0[rr * 64 + p];
        __syncthreads();
        if (rr != p) {
#pragma unroll
            for (int c = 0; c < 16; ++c)
                w0[rr * 64 + cs + c] = fmaf(-f, w0[p * 64 + cs + c], w0[rr * 64 + cs + c]);
        }
        __syncthreads();
    }
    for (int i = tid; i < 1024; i += 128) w1[i] = w0[(i >> 5) * 64 + 32 + (i & 31)];
    __syncthreads();

    // ---- stage 2: E = Pinv H^T  (32 x 64) ----
    for (int i = tid; i < 2048; i += 128) {
        int r = i >> 6, c = i & 63;
        float s = 0.0f;
#pragma unroll 8
        for (int k = 0; k < 32; ++k) s = fmaf(w1[r * 32 + k], H[c * 32 + k], s);
        w2[i] = s;
    }
    __syncthreads();

    // ---- stage 3: D = H E (64x64 -> w3) ; C = E H (32x32 -> w0) ----
    for (int i = tid; i < 4096; i += 128) {
        int a = i >> 6, c = i & 63;
        float s0 = 0.0f, s1 = 0.0f;
        for (int k = 0; k < 32; k += 2) {
            s0 = fmaf(H[a * 32 + k],     w2[k * 64 + c],       s0);
            s1 = fmaf(H[a * 32 + k + 1], w2[(k + 1) * 64 + c], s1);
        }
        w3[i] = s0 + s1;
    }
    for (int i = tid; i < 1024; i += 128) {
        int r = i >> 5, c = i & 31;
        float s0 = 0.0f, s1 = 0.0f;
        for (int m = 0; m < 64; m += 2) {
            s0 = fmaf(w2[r * 64 + m],     H[m * 32 + c],       s0);
            s1 = fmaf(w2[r * 64 + m + 1], H[(m + 1) * 32 + c], s1);
        }
        w0[i] = s0 + s1;
    }
    __syncthreads();

    // ---- stage 4: normalize C, 13 squarings -> rank-1 ----
    {
        float loc = 0.0f;
        for (int i = tid; i < 1024; i += 128) loc = fmaxf(loc, fabsf(w0[i]));
        loc = warpMax(loc);
        if ((tid & 31) == 0) sred4[tid >> 5] = loc;
        __syncthreads();
        float m = fmaxf(fmaxf(sred4[0], sred4[1]), fmaxf(sred4[2], sred4[3]));
        float inv = 1.0f / m;
        for (int i = tid; i < 1024; i += 128) w0[i] *= inv;
        __syncthreads();
    }
    {
        const int r8 = tid >> 2, c8 = (tid & 3) << 3;
        float* cur = w0;
        float* nxt = w0 + 1024;
        for (int s = 0; s < 13; ++s) {
            float acc[8] = {0, 0, 0, 0, 0, 0, 0, 0};
            for (int k = 0; k < 32; ++k) {
                float a = cur[r8 * 32 + k];
#pragma unroll
                for (int j = 0; j < 8; ++j)
                    acc[j] = fmaf(a, cur[k * 32 + c8 + j], acc[j]);
            }
            float loc = 0.0f;
#pragma unroll
            for (int j = 0; j < 8; ++j) loc = fmaxf(loc, fabsf(acc[j]));
            loc = warpMax(loc);
            if ((tid & 31) == 0) sred4[tid >> 5] = loc;
            __syncthreads();
            float m = fmaxf(fmaxf(sred4[0], sred4[1]), fmaxf(sred4[2], sred4[3]));
            float inv = 1.0f / m;
#pragma unroll
            for (int j = 0; j < 8; ++j) nxt[r8 * 32 + c8 + j] = acc[j] * inv;
            __syncthreads();
            float* t = cur; cur = nxt; nxt = t;
        }
        // ---- stage 5: dominant column u; y = H u; Rayleigh on D ----
        if (tid < 32) {
            float s = 0.0f;
            for (int i = 0; i < 32; ++i) { float v = cur[i * 32 + tid]; s = fmaf(v, v, s); }
            sy[tid] = s;
        }
        __syncthreads();
        if (tid == 0) {
            int bj = 0; float bm = -1.0f;
            for (int j = 0; j < 32; ++j) if (sy[j] > bm) { bm = sy[j]; bj = j; }
            sidx = bj;
        }
        __syncthreads();
        if (tid < 64) {
            float s = 0.0f;
            for (int i = 0; i < 32; ++i) s = fmaf(H[tid * 32 + i], cur[i * 32 + sidx], s);
            sy[tid] = s;
        }
        __syncthreads();
        if (tid < 64) {
            float s = 0.0f;
            for (int k = 0; k < 64; ++k) s = fmaf(w3[tid * 64 + k], sy[k], s);
            sz[tid] = s;
        }
        __syncthreads();
        float p1 = (tid < 64) ? sy[tid] * sz[tid] : 0.0f;
        float p2 = (tid < 64) ? sy[tid] * sy[tid] : 0.0f;
        p1 = warpSum(p1);
        p2 = warpSum(p2);
        if ((tid & 31) == 0) { sy[tid >> 5] = p1; sz[tid >> 5] = p2; }
        __syncthreads();
        if (tid == 0) {
            float num = (sy[0] + sy[1]) + (sy[2] + sy[3]);
            float den = (sz[0] + sz[1]) + (sz[2] + sz[3]);
            sTf = BETA * den / num;     // t = beta / lambda_max
        }
    }
    __syncthreads();

    // ---- stage 6: invert G = H^T H (reuse w0, Ginv -> w1) ----
    for (int i = tid; i < 2048; i += 128) {
        int r = i >> 6, c = i & 63;
        if (c < 32) {
            float s0 = 0.0f, s1 = 0.0f;
            for (int m = 0; m < 64; m += 2) {
                s0 = fmaf(H[m * 32 + r],       H[m * 32 + c],       s0);
                s1 = fmaf(H[(m + 1) * 32 + r], H[(m + 1) * 32 + c], s1);
            }
            w0[i] = s0 + s1;
        } else {
            w0[i] = (c - 32 == r) ? 1.0f : 0.0f;
        }
    }
    __syncthreads();
    for (int p = 0; p < 32; ++p) {
        float pv = w0[p * 64 + p];
        float ipv = 1.0f / pv;
        __syncthreads();
        if (tid < 64) w0[p * 64 + tid] *= ipv;
        __syncthreads();
        int rr = tid >> 2, cs = (tid & 3) * 16;
        float f = w0[rr * 64 + p];
        __syncthreads();
        if (rr != p) {
#pragma unroll
            for (int c = 0; c < 16; ++c)
                w0[rr * 64 + cs + c] = fmaf(-f, w0[p * 64 + cs + c], w0[rr * 64 + cs + c]);
        }
        __syncthreads();
    }
    for (int i = tid; i < 1024; i += 128) w1[i] = w0[(i >> 5) * 64 + 32 + (i & 31)];
    __syncthreads();

    // ---- stage 7: Hinv = Ginv H^T -> w4 (stride 68) ----
    for (int i = tid; i < 2048; i += 128) {
        int r = i >> 6, c = i & 63;
        float s = 0.0f;
#pragma unroll 8
        for (int k = 0; k < 32; ++k) s = fmaf(w1[r * 32 + k], H[c * 32 + k], s);
        w4[r * 68 + c] = s;
    }
    __syncthreads();

    // ================= PHASE 2: iteration, warp-per-row =================
    const int iters = *itp;
    const size_t K = (size_t)iters + 1;
    const int w = tid >> 5;
    const int l = tid & 31;
    const int r = blockIdx.x * 4 + w;

    // X ping-pong lives in w0 (free after preproc): [2][4][132]
    float* Xbase = w0;

    // D rows 2l, 2l+1 into registers (f32x2 packed over k)
    unsigned long long d0[32], d1[32];
#pragma unroll
    for (int kk = 0; kk < 32; ++kk) {
        d0[kk] = *reinterpret_cast<const unsigned long long*>(&w3[(2 * l)     * 64 + 2 * kk]);
        d1[kk] = *reinterpret_cast<const unsigned long long*>(&w3[(2 * l + 1) * 64 + 2 * kk]);
    }

    const float tf  = sTf;
    const float a2t = 2.0f * ALPHA * tf;
    const float c22 = 1.0f - a2t;

    // mu for own columns 2l, 2l+1
    float2 mu2;
    {
        float s0 = 0.0f, s1 = 0.0f;
#pragma unroll 8
        for (int i = 0; i < 32; ++i) {
            float qi = q[r * 32 + i];
            float2 ev = *reinterpret_cast<const float2*>(&w2[i * 64 + 2 * l]);
            s0 = fmaf(qi, ev.x, s0);
            s1 = fmaf(qi, ev.y, s1);
        }
        float2 bv = *reinterpret_cast<const float2*>(&b[r * 64 + 2 * l]);
        mu2.x = tf * (s0 - bv.x);
        mu2.y = tf * (s1 - bv.y);
    }
    const float2 b2 = make_float2(-2.0f * ALPHA * mu2.x, -2.0f * ALPHA * mu2.y);

    // c_l = Hinv[l,:] . b[r,:]   (FULL 64-element dot: stride 4, 16 steps)
    const float* hr = &w4[l * 68];
    float cl;
    {
        unsigned long long c0 = 0ull, c1 = 0ull;
#pragma unroll
        for (int m = 0; m < 8; ++m) {
            ulonglong2 bv0 = *reinterpret_cast<const ulonglong2*>(&b[r * 64 + 8 * m]);
            ulonglong2 bv1 = *reinterpret_cast<const ulonglong2*>(&b[r * 64 + 8 * m + 4]);
            ulonglong2 hv0 = *reinterpret_cast<const ulonglong2*>(&hr[8 * m]);
            ulonglong2 hv1 = *reinterpret_cast<const ulonglong2*>(&hr[8 * m + 4]);
            c0 = ffma2(hv0.x, bv0.x, c0);
            c1 = ffma2(hv0.y, bv0.y, c1);
            c0 = ffma2(hv1.x, bv1.x, c0);
            c1 = ffma2(hv1.y, bv1.y, c1);
        }
        cl = hsum2(c0) + hsum2(c1);
    }

    float* xo = out + (size_t)r * K * 128;
    float* po = out + (size_t)BSZ * K * 128 + (size_t)r * K * 32;

    // k = 0 outputs + state
    float2 x1o = make_float2(0.f, 0.f), x2o = make_float2(0.f, 0.f);
    float* X0 = Xbase + 0 * 528 + w * 132;
    *reinterpret_cast<float4*>(&X0[4 * l]) = make_float4(0.f, 0.f, 0.f, 0.f);
    __stcs(reinterpret_cast<float2*>(&xo[2 * l]),      make_float2(0.f, 0.f));
    __stcs(reinterpret_cast<float2*>(&xo[64 + 2 * l]), make_float2(0.f, 0.f));
    __syncwarp();

    float2 n1 = make_float2(0.f, 0.f), n2 = make_float2(0.f, 0.f);
    float pv = -cl;
    int kconv = iters + 1;

    for (int k = 1; k <= iters; ++k) {
        float* Xr = Xbase + ((k - 1) & 1) * 528 + w * 132;
        float* Xw = Xbase + (k & 1) * 528 + w * 132;

        unsigned long long a0 = 0ull, a1 = 0ull, a2v = 0ull, a3 = 0ull;
        unsigned long long p0 = 0ull, p1 = 0ull;
#pragma unroll
        for (int q4 = 0; q4 < 16; ++q4) {
            ulonglong2 xv = *reinterpret_cast<ulonglong2*>(&Xr[4 * q4]);        // x1
            ulonglong2 yv = *reinterpret_cast<ulonglong2*>(&Xr[64 + 4 * q4]);   // x2
            ulonglong2 hv = *reinterpret_cast<const ulonglong2*>(&hr[4 * q4]);  // Hinv
            a0  = ffma2(d0[2 * q4],     xv.x, a0);
            a1  = ffma2(d0[2 * q4 + 1], xv.y, a1);
            a2v = ffma2(d1[2 * q4],     xv.x, a2v);
            a3  = ffma2(d1[2 * q4 + 1], xv.y, a3);
            p0  = ffma2(hv.x, yv.x, p0);
            p1  = ffma2(hv.y, yv.y, p1);
        }
        float w0s = hsum2(a0)  + hsum2(a1);
        float w1s = hsum2(a2v) + hsum2(a3);
        pv = (hsum2(p0) + hsum2(p1)) - cl;                 // primal_{k-1}[l]
        __stcs(&po[(size_t)(k - 1) * 32 + l], pv);

        float2 m1, m2;
        m1.x = fmaf(tf, w0s + x2o.x, mu2.x);
        m1.y = fmaf(tf, w1s + x2o.y, mu2.y);
        m2.x = fmaxf(fmaf(-a2t, w0s, fmaf(c22, x2o.x, x1o.x)) + b2.x, 0.0f);
        m2.y = fmaxf(fmaf(-a2t, w1s, fmaf(c22, x2o.y, x1o.y)) + b2.y, 0.0f);

        bool conv = (m1.x == x1o.x) & (m1.y == x1o.y) &
                    (m2.x == x2o.x) & (m2.y == x2o.y);
        n1 = m1; n2 = m2;
        x1o = m1; x2o = m2;

        *reinterpret_cast<float2*>(&Xw[2 * l])      = m1;
        *reinterpret_cast<float2*>(&Xw[64 + 2 * l]) = m2;
        float* xok = xo + (size_t)k * 128;
        __stcs(reinterpret_cast<float2*>(&xok[2 * l]),      m1);
        __stcs(reinterpret_cast<float2*>(&xok[64 + 2 * l]), m2);

        if (__all_sync(0xffffffffu, conv)) { kconv = k; break; }
        __syncwarp();
    }

    if (kconv <= iters) {
        // exact fixed point: remaining iterates/primals are identical -> stream stores
#pragma unroll 4
        for (int kk = kconv + 1; kk <= iters; ++kk) {
            float* xok = xo + (size_t)kk * 128;
            __stcs(reinterpret_cast<float2*>(&xok[2 * l]),      n1);
            __stcs(reinterpret_cast<float2*>(&xok[64 + 2 * l]), n2);
        }
#pragma unroll 4
        for (int kk = kconv; kk <= iters; ++kk)
            __stcs(&po[(size_t)kk * 32 + l], pv);
    } else {
        // final primal for k = iters
        float* Xr = Xbase + (iters & 1) * 528 + w * 132;
        unsigned long long p0 = 0ull, p1 = 0ull;
#pragma unroll
        for (int q4 = 0; q4 < 16; ++q4) {
            ulonglong2 yv = *reinterpret_cast<ulonglong2*>(&Xr[64 + 4 * q4]);
            ulonglong2 hv = *reinterpret_cast<const ulonglong2*>(&hr[4 * q4]);
            p0 = ffma2(hv.x, yv.x, p0);
            p1 = ffma2(hv.y, yv.y, p1);
        }
        __stcs(&po[(size_t)iters * 32 + l], (hsum2(p0) + hsum2(p1)) - cl);
    }
}

// ----------------------------- launch -----------------------------
extern "C" void kernel_launch(void* const* d_in, const int* in_sizes, int n_in,
                              void* d_out, int out_size) {
    (void)in_sizes; (void)out_size;
    const float* q = (const float*)d_in[0];
    const float* b = (const float*)d_in[1];
    const float* P = (const float*)d_in[2];
    const float* H = (const float*)d_in[3];

    const int* itp;
    if (n_in >= 5) {
        itp = (const int*)d_in[4];
    } else {
        void* p = nullptr;
        cudaGetSymbolAddress(&p, gItersDefault);
        itp = (const int*)p;
    }
    float* out = (float*)d_out;

    qp_fused_kernel<<<128, 128>>>(itp, q, b, P, H, out);
}

// round 6
// speedup vs baseline: 2.6198x; 1.1868x over previous
#include <cuda_runtime.h>
#include <cstdint>

#define N32   32
#define M64   64
#define BSZ   512
#define ALPHA 1.0f
#define BETA  1.0f

__device__ int gItersDefault = 1000;

// ----------------------------- helpers -----------------------------
__device__ __forceinline__ unsigned long long ffma2(unsigned long long a,
                                                    unsigned long long b,
                                                    unsigned long long c) {
    unsigned long long d;
    asm("fma.rn.f32x2 %0, %1, %2, %3;" : "=l"(d) : "l"(a), "l"(b), "l"(c));
    return d;
}
__device__ __forceinline__ float hsum2(unsigned long long a) {
    float lo, hi;
    asm("mov.b64 {%0, %1}, %2;" : "=f"(lo), "=f"(hi) : "l"(a));
    return lo + hi;
}
__device__ __forceinline__ float warpMax(float v) {
#pragma unroll
    for (int o = 16; o; o >>= 1) v = fmaxf(v, __shfl_xor_sync(0xffffffffu, v, o));
    return v;
}
__device__ __forceinline__ float warpSum(float v) {
#pragma unroll
    for (int o = 16; o; o >>= 1) v += __shfl_xor_sync(0xffffffffu, v, o);
    return v;
}

// ----------------------------- fused kernel -----------------------------
// grid = 128 CTAs x 128 threads. Phase 1: every CTA redundantly preprocesses in
// its own smem (H cached in smem; avoids gmem-latency-bound chains).
// Phase 2: warp-per-row iteration, D rows in registers, Hinv in smem with a
// conflict-free per-lane 16B-tile layout.
//
// Shared layout (floats):
//   w0 [0:2048)       GJ workspace / C squaring buffers / later X ping-pong
//   w1 [2048:3072)    Pinv, later Ginv
//   w2 [3072:5120)    E = Pinv H^T
//   w3 [5120:9216)    D = H Pinv H^T
//   w4 [9216:11264)   Ht: Hinv transposed tiles  Ht[m][lane][e] = Hinv[lane][4m+e]
//   sH [2048]         H cache
__global__ void __launch_bounds__(128, 1)
qp_fused_kernel(const int* __restrict__ itp,
                const float* __restrict__ q, const float* __restrict__ b,
                const float* __restrict__ P, const float* __restrict__ Hg,
                float* __restrict__ out) {
    __shared__ __align__(16) float buf[11264];
    __shared__ __align__(16) float sH[2048];
    __shared__ float sred4[4];
    __shared__ float sy[64], sz[64];
    __shared__ float sTf;
    __shared__ int sidx;

    float* w0 = buf;
    float* w1 = buf + 2048;
    float* w2 = buf + 3072;
    float* w3 = buf + 5120;
    float* Ht = buf + 9216;

    const int tid = threadIdx.x;

    // ---- cache H in smem ----
    for (int i = tid; i < 2048; i += 128) sH[i] = Hg[i];

    // ================= PHASE 1: preprocessing (redundant per CTA) =================
    // ---- stage 1: invert P ----
    for (int i = tid; i < 2048; i += 128) {
        int r = i >> 6, c = i & 63;
        w0[i] = (c < 32) ? P[r * 32 + c] : ((c - 32 == r) ? 1.0f : 0.0f);
    }
    __syncthreads();
    for (int p = 0; p < 32; ++p) {
        float pv = w0[p * 64 + p];
        float ipv = 1.0f / pv;
        __syncthreads();
        if (tid < 64) w0[p * 64 + tid] *= ipv;
        __syncthreads();
        int rr = tid >> 2, cs = (tid & 3) * 16;
        float f = w0[rr * 64 + p];
        __syncthreads();
        if (rr != p) {
#pragma unroll
            for (int c = 0; c < 16; ++c)
                w0[rr * 64 + cs + c] = fmaf(-f, w0[p * 64 + cs + c], w0[rr * 64 + cs + c]);
        }
        __syncthreads();
    }
    for (int i = tid; i < 1024; i += 128) w1[i] = w0[(i >> 5) * 64 + 32 + (i & 31)];
    __syncthreads();

    // ---- stage 2: E = Pinv H^T ----
    for (int i = tid; i < 2048; i += 128) {
        int r = i >> 6, c = i & 63;
        float s = 0.0f;
#pragma unroll 8
        for (int k = 0; k < 32; ++k) s = fmaf(w1[r * 32 + k], sH[c * 32 + k], s);
        w2[i] = s;
    }
    __syncthreads();

    // ---- stage 3: D = H E -> w3 ; C = E H -> w0 ----
    for (int i = tid; i < 4096; i += 128) {
        int a = i >> 6, c = i & 63;
        float s0 = 0.0f, s1 = 0.0f;
        for (int k = 0; k < 32; k += 2) {
            s0 = fmaf(sH[a * 32 + k],     w2[k * 64 + c],       s0);
            s1 = fmaf(sH[a * 32 + k + 1], w2[(k + 1) * 64 + c], s1);
        }
        w3[i] = s0 + s1;
    }
    for (int i = tid; i < 1024; i += 128) {
        int r = i >> 5, c = i & 31;
        float s0 = 0.0f, s1 = 0.0f;
        for (int m = 0; m < 64; m += 2) {
            s0 = fmaf(w2[r * 64 + m],     sH[m * 32 + c],       s0);
            s1 = fmaf(w2[r * 64 + m + 1], sH[(m + 1) * 32 + c], s1);
        }
        w0[i] = s0 + s1;
    }
    __syncthreads();

    // ---- stage 4: normalize C, 13 squarings ----
    {
        float loc = 0.0f;
        for (int i = tid; i < 1024; i += 128) loc = fmaxf(loc, fabsf(w0[i]));
        loc = warpMax(loc);
        if ((tid & 31) == 0) sred4[tid >> 5] = loc;
        __syncthreads();
        float m = fmaxf(fmaxf(sred4[0], sred4[1]), fmaxf(sred4[2], sred4[3]));
        float inv = 1.0f / m;
        for (int i = tid; i < 1024; i += 128) w0[i] *= inv;
        __syncthreads();
    }
    {
        const int r8 = tid >> 2, c8 = (tid & 3) << 3;
        float* cur = w0;
        float* nxt = w0 + 1024;
        for (int s = 0; s < 13; ++s) {
            float acc[8] = {0, 0, 0, 0, 0, 0, 0, 0};
            for (int k = 0; k < 32; ++k) {
                float a = cur[r8 * 32 + k];
#pragma unroll
                for (int j = 0; j < 8; ++j)
                    acc[j] = fmaf(a, cur[k * 32 + c8 + j], acc[j]);
            }
            float loc = 0.0f;
#pragma unroll
            for (int j = 0; j < 8; ++j) loc = fmaxf(loc, fabsf(acc[j]));
            loc = warpMax(loc);
            if ((tid & 31) == 0) sred4[tid >> 5] = loc;
            __syncthreads();
            float m = fmaxf(fmaxf(sred4[0], sred4[1]), fmaxf(sred4[2], sred4[3]));
            float inv = 1.0f / m;
#pragma unroll
            for (int j = 0; j < 8; ++j) nxt[r8 * 32 + c8 + j] = acc[j] * inv;
            __syncthreads();
            float* t = cur; cur = nxt; nxt = t;
        }
        // ---- stage 5: dominant column u; y = H u; Rayleigh ----
        if (tid < 32) {
            float s = 0.0f;
            for (int i = 0; i < 32; ++i) { float v = cur[i * 32 + tid]; s = fmaf(v, v, s); }
            sy[tid] = s;
        }
        __syncthreads();
        if (tid == 0) {
            int bj = 0; float bm = -1.0f;
            for (int j = 0; j < 32; ++j) if (sy[j] > bm) { bm = sy[j]; bj = j; }
            sidx = bj;
        }
        __syncthreads();
        if (tid < 64) {
            float s = 0.0f;
            for (int i = 0; i < 32; ++i) s = fmaf(sH[tid * 32 + i], cur[i * 32 + sidx], s);
            sy[tid] = s;
        }
        __syncthreads();
        if (tid < 64) {
            float s = 0.0f;
            for (int k = 0; k < 64; ++k) s = fmaf(w3[tid * 64 + k], sy[k], s);
            sz[tid] = s;
        }
        __syncthreads();
        float p1 = (tid < 64) ? sy[tid] * sz[tid] : 0.0f;
        float p2 = (tid < 64) ? sy[tid] * sy[tid] : 0.0f;
        p1 = warpSum(p1);
        p2 = warpSum(p2);
        if ((tid & 31) == 0) { sy[tid >> 5] = p1; sz[tid >> 5] = p2; }
        __syncthreads();
        if (tid == 0) {
            float num = (sy[0] + sy[1]) + (sy[2] + sy[3]);
            float den = (sz[0] + sz[1]) + (sz[2] + sz[3]);
            sTf = BETA * den / num;     // t = beta / lambda_max
        }
    }
    __syncthreads();

    // ---- stage 6: invert G = H^T H ----
    for (int i = tid; i < 2048; i += 128) {
        int r = i >> 6, c = i & 63;
        if (c < 32) {
            float s0 = 0.0f, s1 = 0.0f;
            for (int m = 0; m < 64; m += 2) {
                s0 = fmaf(sH[m * 32 + r],       sH[m * 32 + c],       s0);
                s1 = fmaf(sH[(m + 1) * 32 + r], sH[(m + 1) * 32 + c], s1);
            }
            w0[i] = s0 + s1;
        } else {
            w0[i] = (c - 32 == r) ? 1.0f : 0.0f;
        }
    }
    __syncthreads();
    for (int p = 0; p < 32; ++p) {
        float pv = w0[p * 64 + p];
        float ipv = 1.0f / pv;
        __syncthreads();
        if (tid < 64) w0[p * 64 + tid] *= ipv;
        __syncthreads();
        int rr = tid >> 2, cs = (tid & 3) * 16;
        float f = w0[rr * 64 + p];
        __syncthreads();
        if (rr != p) {
#pragma unroll
            for (int c = 0; c < 16; ++c)
                w0[rr * 64 + cs + c] = fmaf(-f, w0[p * 64 + cs + c], w0[rr * 64 + cs + c]);
        }
        __syncthreads();
    }
    for (int i = tid; i < 1024; i += 128) w1[i] = w0[(i >> 5) * 64 + 32 + (i & 31)];
    __syncthreads();

    // ---- stage 7: Hinv = Ginv H^T -> Ht transposed tiles ----
    // Ht[m][lane][e] = Hinv[lane][4m+e]  -> float index (c>>2)*128 + r*4 + (c&3)
    for (int i = tid; i < 2048; i += 128) {
        int r = i >> 6, c = i & 63;
        float s = 0.0f;
#pragma unroll 8
        for (int k = 0; k < 32; ++k) s = fmaf(w1[r * 32 + k], sH[c * 32 + k], s);
        Ht[(c >> 2) * 128 + r * 4 + (c & 3)] = s;
    }
    __syncthreads();

    // ================= PHASE 2: iteration, warp-per-row =================
    const int iters = *itp;
    const size_t K = (size_t)iters + 1;
    const int w = tid >> 5;
    const int l = tid & 31;
    const int r = blockIdx.x * 4 + w;

    float* Xbase = w0;   // ping-pong [2][4][132]

    // D rows 2l, 2l+1 into registers (f32x2 packed over k)
    unsigned long long d0[32], d1[32];
#pragma unroll
    for (int kk = 0; kk < 32; ++kk) {
        d0[kk] = *reinterpret_cast<const unsigned long long*>(&w3[(2 * l)     * 64 + 2 * kk]);
        d1[kk] = *reinterpret_cast<const unsigned long long*>(&w3[(2 * l + 1) * 64 + 2 * kk]);
    }

    const float tf  = sTf;
    const float a2t = 2.0f * ALPHA * tf;
    const float c22 = 1.0f - a2t;

    // mu for own columns 2l, 2l+1
    float2 mu2;
    {
        float s0 = 0.0f, s1 = 0.0f;
#pragma unroll 8
        for (int i = 0; i < 32; ++i) {
            float qi = q[r * 32 + i];
            float2 ev = *reinterpret_cast<const float2*>(&w2[i * 64 + 2 * l]);
            s0 = fmaf(qi, ev.x, s0);
            s1 = fmaf(qi, ev.y, s1);
        }
        float2 bv = *reinterpret_cast<const float2*>(&b[r * 64 + 2 * l]);
        mu2.x = tf * (s0 - bv.x);
        mu2.y = tf * (s1 - bv.y);
    }
    const float2 b2 = make_float2(-2.0f * ALPHA * mu2.x, -2.0f * ALPHA * mu2.y);

    // c_l = Hinv[l,:] . b[r,:]  via Ht tiles
    float cl;
    {
        unsigned long long c0 = 0ull, c1 = 0ull;
#pragma unroll
        for (int m = 0; m < 16; ++m) {
            ulonglong2 bv = *reinterpret_cast<const ulonglong2*>(&b[r * 64 + 4 * m]);
            ulonglong2 hv = *reinterpret_cast<const ulonglong2*>(&Ht[m * 128 + 4 * l]);
            c0 = ffma2(hv.x, bv.x, c0);
            c1 = ffma2(hv.y, bv.y, c1);
        }
        cl = hsum2(c0) + hsum2(c1);
    }

    float* xo = out + (size_t)r * K * 128;
    float* po = out + (size_t)BSZ * K * 128 + (size_t)r * K * 32;

    // k = 0 outputs + state
    float2 x1o = make_float2(0.f, 0.f), x2o = make_float2(0.f, 0.f);
    float* X0 = Xbase + 0 * 528 + w * 132;
    *reinterpret_cast<float4*>(&X0[4 * l]) = make_float4(0.f, 0.f, 0.f, 0.f);
    __stcs(reinterpret_cast<float2*>(&xo[2 * l]),      make_float2(0.f, 0.f));
    __stcs(reinterpret_cast<float2*>(&xo[64 + 2 * l]), make_float2(0.f, 0.f));
    __syncwarp();

    float2 n1 = make_float2(0.f, 0.f), n2 = make_float2(0.f, 0.f);
    float pv = -cl;
    int kconv = iters + 1;

    for (int k = 1; k <= iters; ++k) {
        float* Xr = Xbase + ((k - 1) & 1) * 528 + w * 132;
        float* Xw = Xbase + (k & 1) * 528 + w * 132;

        unsigned long long a0 = 0ull, a1 = 0ull, a2v = 0ull, a3 = 0ull;
        unsigned long long p0 = 0ull, p1 = 0ull;
#pragma unroll
        for (int q4 = 0; q4 < 16; ++q4) {
            ulonglong2 xv = *reinterpret_cast<ulonglong2*>(&Xr[4 * q4]);          // x1 bcast
            ulonglong2 yv = *reinterpret_cast<ulonglong2*>(&Xr[64 + 4 * q4]);     // x2 bcast
            ulonglong2 hv = *reinterpret_cast<const ulonglong2*>(&Ht[q4 * 128 + 4 * l]);  // conflict-free
            a0  = ffma2(d0[2 * q4],     xv.x, a0);
            a1  = ffma2(d0[2 * q4 + 1], xv.y, a1);
            a2v = ffma2(d1[2 * q4],     xv.x, a2v);
            a3  = ffma2(d1[2 * q4 + 1], xv.y, a3);
            p0  = ffma2(hv.x, yv.x, p0);
            p1  = ffma2(hv.y, yv.y, p1);
        }
        float w0s = hsum2(a0)  + hsum2(a1);
        float w1s = hsum2(a2v) + hsum2(a3);
        pv = (hsum2(p0) + hsum2(p1)) - cl;                 // primal_{k-1}[l]
        __stcs(&po[(size_t)(k - 1) * 32 + l], pv);

        float2 m1, m2;
        m1.x = fmaf(tf, w0s + x2o.x, mu2.x);
        m1.y = fmaf(tf, w1s + x2o.y, mu2.y);
        m2.x = fmaxf(fmaf(-a2t, w0s, fmaf(c22, x2o.x, x1o.x)) + b2.x, 0.0f);
        m2.y = fmaxf(fmaf(-a2t, w1s, fmaf(c22, x2o.y, x1o.y)) + b2.y, 0.0f);

        bool conv = (m1.x == x1o.x) & (m1.y == x1o.y) &
                    (m2.x == x2o.x) & (m2.y == x2o.y);
        n1 = m1; n2 = m2;
        x1o = m1; x2o = m2;

        *reinterpret_cast<float2*>(&Xw[2 * l])      = m1;
        *reinterpret_cast<float2*>(&Xw[64 + 2 * l]) = m2;
        float* xok = xo + (size_t)k * 128;
        __stcs(reinterpret_cast<float2*>(&xok[2 * l]),      m1);
        __stcs(reinterpret_cast<float2*>(&xok[64 + 2 * l]), m2);

        if (__all_sync(0xffffffffu, conv)) { kconv = k; break; }
        __syncwarp();
    }

    if (kconv <= iters) {
        // exact fixed point: remaining outputs identical -> stream stores
#pragma unroll 4
        for (int kk = kconv + 1; kk <= iters; ++kk) {
            float* xok = xo + (size_t)kk * 128;
            __stcs(reinterpret_cast<float2*>(&xok[2 * l]),      n1);
            __stcs(reinterpret_cast<float2*>(&xok[64 + 2 * l]), n2);
        }
#pragma unroll 4
        for (int kk = kconv; kk <= iters; ++kk)
            __stcs(&po[(size_t)kk * 32 + l], pv);
    } else {
        // final primal for k = iters
        float* Xr = Xbase + (iters & 1) * 528 + w * 132;
        unsigned long long p0 = 0ull, p1 = 0ull;
#pragma unroll
        for (int q4 = 0; q4 < 16; ++q4) {
            ulonglong2 yv = *reinterpret_cast<ulonglong2*>(&Xr[64 + 4 * q4]);
            ulonglong2 hv = *reinterpret_cast<const ulonglong2*>(&Ht[q4 * 128 + 4 * l]);
            p0 = ffma2(hv.x, yv.x, p0);
            p1 = ffma2(hv.y, yv.y, p1);
        }
        __stcs(&po[(size_t)iters * 32 + l], (hsum2(p0) + hsum2(p1)) - cl);
    }
}

// ----------------------------- launch -----------------------------
extern "C" void kernel_launch(void* const* d_in, const int* in_sizes, int n_in,
                              void* d_out, int out_size) {
    (void)in_sizes; (void)out_size;
    const float* q = (const float*)d_in[0];
    const float* b = (const float*)d_in[1];
    const float* P = (const float*)d_in[2];
    const float* H = (const float*)d_in[3];

    const int* itp;
    if (n_in >= 5) {
        itp = (const int*)d_in[4];
    } else {
        void* p = nullptr;
        cudaGetSymbolAddress(&p, gItersDefault);
        itp = (const int*)p;
    }
    float* out = (float*)d_out;

    qp_fused_kernel<<<128, 128>>>(itp, q, b, P, H, out);
}